// round 5
// baseline (speedup 1.0000x reference)
#include <cuda_runtime.h>
#include <cuda_bf16.h>

#define SEQ  2048
#define DIM  1024
#define BATCH 4
#define BM 128
#define BN 128
#define BK 8

// Scratch (allocation-free rule: __device__ globals)
__device__ float g_q[(size_t)BATCH * SEQ * DIM];   // 32 MB
__device__ float g_k[(size_t)BATCH * SEQ * DIM];   // 32 MB
__device__ float g_v[(size_t)BATCH * SEQ * DIM];   // 32 MB
__device__ float g_s[(size_t)BATCH * SEQ * SEQ];   // 64 MB (scores -> attn in place)

// ---------------------------------------------------------------------------
// 128x128 fp32 GEMM tile, 256 threads, 8x8 per thread, BK=8,
// register prefetch of the next k-slab. BT=true means C = A * B^T
// (B rows indexed by the N dimension, k contiguous — used for Q·K^T).
// ---------------------------------------------------------------------------
template <bool BT>
__device__ __forceinline__ void gemm128(
    const float* __restrict__ A, const float* __restrict__ B,
    float* __restrict__ C,
    int lda, int ldb, int ldc, int kmax, float alpha, int m0, int n0)
{
    __shared__ float As[BK][BM];
    __shared__ float Bs[BK][BN];
    const int tid = threadIdx.x;

    // A tile loader: 128 rows x 8 k, one float4 per thread, transposed into As[k][m]
    const int arow = tid >> 1;
    const int ak   = (tid & 1) << 2;
    const float* Ap = A + (size_t)(m0 + arow) * lda + ak;

    // B tile loader
    int b0i, b1i;
    const float* Bp;
    if (BT) {
        b0i = tid >> 1;            // key row within tile (N dim)
        b1i = (tid & 1) << 2;      // k offset
        Bp = B + (size_t)(n0 + b0i) * ldb + b1i;
    } else {
        b0i = tid >> 5;            // k row 0..7
        b1i = (tid & 31) << 2;     // col offset
        Bp = B + (size_t)b0i * ldb + n0 + b1i;
    }

    // compute mapping: 16x16 threads, each owns (tm..tm+3, tm+64..tm+67) x (tn..., tn+64...)
    const int tm = (tid & 15) << 2;
    const int tn = (tid >> 4) << 2;

    float acc[8][8];
#pragma unroll
    for (int i = 0; i < 8; i++)
#pragma unroll
        for (int j = 0; j < 8; j++) acc[i][j] = 0.f;

    float4 pa = *(const float4*)Ap;
    float4 pb = *(const float4*)Bp;

    for (int k0 = 0; k0 < kmax; k0 += BK) {
        // commit prefetched regs to smem
        As[ak + 0][arow] = pa.x; As[ak + 1][arow] = pa.y;
        As[ak + 2][arow] = pa.z; As[ak + 3][arow] = pa.w;
        if (BT) {
            Bs[b1i + 0][b0i] = pb.x; Bs[b1i + 1][b0i] = pb.y;
            Bs[b1i + 2][b0i] = pb.z; Bs[b1i + 3][b0i] = pb.w;
        } else {
            *(float4*)&Bs[b0i][b1i] = pb;
        }
        __syncthreads();

        // prefetch next k-slab while computing this one
        if (k0 + BK < kmax) {
            pa = *(const float4*)(Ap + k0 + BK);
            pb = BT ? *(const float4*)(Bp + k0 + BK)
                    : *(const float4*)(Bp + (size_t)(k0 + BK) * ldb);
        }

#pragma unroll
        for (int kk = 0; kk < BK; kk++) {
            float4 a0 = *(const float4*)&As[kk][tm];
            float4 a1 = *(const float4*)&As[kk][tm + 64];
            float4 b0 = *(const float4*)&Bs[kk][tn];
            float4 b1 = *(const float4*)&Bs[kk][tn + 64];
            float ar[8] = {a0.x, a0.y, a0.z, a0.w, a1.x, a1.y, a1.z, a1.w};
            float br[8] = {b0.x, b0.y, b0.z, b0.w, b1.x, b1.y, b1.z, b1.w};
#pragma unroll
            for (int i = 0; i < 8; i++)
#pragma unroll
                for (int j = 0; j < 8; j++)
                    acc[i][j] += ar[i] * br[j];
        }
        __syncthreads();
    }

#pragma unroll
    for (int i = 0; i < 8; i++) {
        const int row = m0 + tm + ((i < 4) ? i : 60 + i);  // tm+i or tm+64+(i-4)
        float4 v0, v1;
        v0.x = acc[i][0] * alpha; v0.y = acc[i][1] * alpha;
        v0.z = acc[i][2] * alpha; v0.w = acc[i][3] * alpha;
        v1.x = acc[i][4] * alpha; v1.y = acc[i][5] * alpha;
        v1.z = acc[i][6] * alpha; v1.w = acc[i][7] * alpha;
        *(float4*)&C[(size_t)row * ldc + n0 + tn]      = v0;
        *(float4*)&C[(size_t)row * ldc + n0 + tn + 64] = v1;
    }
}

// ---------------------------------------------------------------------------
// Kernel 1: Q/K/V projection. grid = (DIM/BN, B*S/BM, 3), z picks the weight.
// ---------------------------------------------------------------------------
__global__ __launch_bounds__(256, 2)
void qkv_kernel(const float* __restrict__ x,
                const float* __restrict__ Wq,
                const float* __restrict__ Wk,
                const float* __restrict__ Wv)
{
    const int z = blockIdx.z;
    const float* W = (z == 0) ? Wq : (z == 1) ? Wk : Wv;
    float* Cout    = (z == 0) ? g_q : (z == 1) ? g_k : g_v;
    gemm128<false>(x, W, Cout, DIM, DIM, DIM, DIM, 1.0f,
                   blockIdx.y * BM, blockIdx.x * BN);
}

// ---------------------------------------------------------------------------
// Kernel 2: scores = (Q K^T) / 32, lower-triangular tiles only (causal).
// Tiles strictly above the diagonal are never touched (softmax ignores them).
// ---------------------------------------------------------------------------
__global__ __launch_bounds__(256, 2)
void scores_kernel()
{
    if ((int)blockIdx.x > (int)blockIdx.y) return;  // col tile > row tile: masked
    const int b = blockIdx.z;
    gemm128<true>(g_q + (size_t)b * SEQ * DIM,
                  g_k + (size_t)b * SEQ * DIM,
                  g_s + (size_t)b * SEQ * SEQ,
                  DIM, DIM, SEQ, DIM, 0.03125f,
                  blockIdx.y * BM, blockIdx.x * BN);
}

// ---------------------------------------------------------------------------
// Kernel 3: causal softmax, in place. One block per (b, i) row; processes
// j in [0, i], writes zeros for j in (i, SEQ) so PV can consume padded tiles.
// ---------------------------------------------------------------------------
__global__ __launch_bounds__(256)
void softmax_kernel()
{
    const int row = blockIdx.x;               // b*SEQ + i
    float* p = g_s + (size_t)row * SEQ;
    const int len = (row & (SEQ - 1)) + 1;    // i + 1
    const int tid = threadIdx.x;
    __shared__ float red[256];

    float m = -1e30f;
    for (int j = tid; j < len; j += 256) m = fmaxf(m, p[j]);
    red[tid] = m; __syncthreads();
    for (int s = 128; s > 0; s >>= 1) {
        if (tid < s) red[tid] = fmaxf(red[tid], red[tid + s]);
        __syncthreads();
    }
    m = red[0];
    __syncthreads();

    float sum = 0.f;
    for (int j = tid; j < len; j += 256) sum += __expf(p[j] - m);
    red[tid] = sum; __syncthreads();
    for (int s = 128; s > 0; s >>= 1) {
        if (tid < s) red[tid] += red[tid + s];
        __syncthreads();
    }
    const float inv = 1.0f / red[0];

    for (int j = tid; j < len; j += 256)       p[j] = __expf(p[j] - m) * inv;
    for (int j = len + tid; j < SEQ; j += 256) p[j] = 0.f;
}

// ---------------------------------------------------------------------------
// Kernel 4: out = P @ V. K-loop bounded at (row_tile+1)*128 (causal).
// ---------------------------------------------------------------------------
__global__ __launch_bounds__(256, 2)
void pv_kernel(float* __restrict__ out)
{
    const int b = blockIdx.z;
    const int kmax = (blockIdx.y + 1) * BM;
    gemm128<false>(g_s + (size_t)b * SEQ * SEQ,
                   g_v + (size_t)b * SEQ * DIM,
                   out + (size_t)b * SEQ * DIM,
                   SEQ, DIM, DIM, kmax, 1.0f,
                   blockIdx.y * BM, blockIdx.x * BN);
}

// ---------------------------------------------------------------------------
extern "C" void kernel_launch(void* const* d_in, const int* in_sizes, int n_in,
                              void* d_out, int out_size)
{
    const float* x  = (const float*)d_in[0];
    const float* Wq = (const float*)d_in[1];
    const float* Wk = (const float*)d_in[2];
    const float* Wv = (const float*)d_in[3];
    float* out = (float*)d_out;

    qkv_kernel<<<dim3(DIM / BN, (BATCH * SEQ) / BM, 3), 256>>>(x, Wq, Wk, Wv);
    scores_kernel<<<dim3(SEQ / BN, SEQ / BM, BATCH), 256>>>();
    softmax_kernel<<<BATCH * SEQ, 256>>>();
    pv_kernel<<<dim3(DIM / BN, SEQ / BM, BATCH), 256>>>(out);
}